// round 16
// baseline (speedup 1.0000x reference)
#include <cuda_runtime.h>
#include <cstdint>

namespace {

constexpr int Bn = 131072;
constexpr int NT = 256;
constexpr int NE = 4;

// global scratch (static __device__ allowed; no runtime alloc)
__device__ float g_a2[(size_t)Bn * 256];   // shared features, 134MB
__device__ int   g_elist[NE][Bn];          // per-expert compact row lists
__device__ int   g_cnt[NE];                // per-expert counts

struct Params {
    const float *x, *bW1, *bb1, *bg1, *bbt1, *bW2, *bb2, *bg2, *bbt2;
    const float *cW1, *cb1, *cg1, *cbt1, *cW2, *cb2, *cg2, *cbt2, *chW, *chb;
    const float *rW1, *rb1, *rg1, *rbt1, *rW2, *rb2, *rg2, *rbt2, *rhW, *rhb;
    float* out;
};

// ---- packed f32x2 helpers (bit-exact per-lane fp32 FMA) ----
__device__ __forceinline__ void ffma2(unsigned long long& d,
                                      unsigned long long a,
                                      unsigned long long b) {
    asm("fma.rn.f32x2 %0, %1, %2, %0;" : "+l"(d) : "l"(a), "l"(b));
}
__device__ __forceinline__ unsigned long long pack2(float v) {
    unsigned long long r;
    asm("mov.b64 %0, {%1, %1};" : "=l"(r) : "f"(v));
    return r;
}
__device__ __forceinline__ void unpack2(unsigned long long v, float& lo, float& hi) {
    asm("mov.b64 {%0, %1}, %2;" : "=f"(lo), "=f"(hi) : "l"(v));
}

// out[row][N] = act[row][K] @ W[K][N] + bias for row < nrows.
// act: ANY space (smem or gmem; warp-broadcast reads), compact stride K.
// W,bias gmem via __ldg. Row map row = rg + i*RG (rg warp-uniform guards).
template<int K, int N, int RT, int TMv>
__device__ __forceinline__ void gemm_g(const float* __restrict__ W,
                                       const float* __restrict__ bias,
                                       const float* act, float* out, int nrows) {
    constexpr int CG = N / 4;
    constexpr int RG = NT / CG;
    static_assert(RG * RT == TMv, "row coverage");

    const int tid = threadIdx.x;
    const int cg = tid % CG;
    const int rg = tid / CG;          // warp-uniform
    const int j0 = cg * 4;

    unsigned long long acc2[RT][2];
#pragma unroll
    for (int i = 0; i < RT; i++) { acc2[i][0] = 0ull; acc2[i][1] = 0ull; }

#pragma unroll 4
    for (int k4 = 0; k4 < K; k4 += 4) {
        ulonglong2 wv[4];
#pragma unroll
        for (int t = 0; t < 4; t++)
            wv[t] = __ldg(reinterpret_cast<const ulonglong2*>(&W[(k4 + t) * N + j0]));
#pragma unroll
        for (int i = 0; i < RT; i++) {
            const int row = rg + i * RG;
            if (row < nrows) {        // warp-uniform
                float4 av = *reinterpret_cast<const float4*>(&act[(size_t)row * K + k4]);
                unsigned long long pa0 = pack2(av.x), pa1 = pack2(av.y);
                unsigned long long pa2 = pack2(av.z), pa3 = pack2(av.w);
                ffma2(acc2[i][0], pa0, wv[0].x); ffma2(acc2[i][1], pa0, wv[0].y);
                ffma2(acc2[i][0], pa1, wv[1].x); ffma2(acc2[i][1], pa1, wv[1].y);
                ffma2(acc2[i][0], pa2, wv[2].x); ffma2(acc2[i][1], pa2, wv[2].y);
                ffma2(acc2[i][0], pa3, wv[3].x); ffma2(acc2[i][1], pa3, wv[3].y);
            }
        }
    }

    const float4 bv = __ldg(reinterpret_cast<const float4*>(&bias[j0]));
#pragma unroll
    for (int i = 0; i < RT; i++) {
        const int row = rg + i * RG;
        if (row < nrows) {
            float a0, a1v, a2v, a3;
            unpack2(acc2[i][0], a0, a1v);
            unpack2(acc2[i][1], a2v, a3);
            out[(size_t)row * N + j0 + 0] = a0  + bv.x;
            out[(size_t)row * N + j0 + 1] = a1v + bv.y;
            out[(size_t)row * N + j0 + 2] = a2v + bv.z;
            out[(size_t)row * N + j0 + 3] = a3  + bv.w;
        }
    }
}

// Same as gemm_g but rows are gathered from gbase via index list (smem).
template<int K, int N, int RT, int TMv>
__device__ __forceinline__ void gemm_idx(const float* __restrict__ W,
                                         const float* __restrict__ bias,
                                         const float* __restrict__ gbase,
                                         const int* rows,
                                         float* out, int nrows) {
    constexpr int CG = N / 4;
    constexpr int RG = NT / CG;
    static_assert(RG * RT == TMv, "row coverage");

    const int tid = threadIdx.x;
    const int cg = tid % CG;
    const int rg = tid / CG;          // warp-uniform
    const int j0 = cg * 4;

    unsigned long long acc2[RT][2];
#pragma unroll
    for (int i = 0; i < RT; i++) { acc2[i][0] = 0ull; acc2[i][1] = 0ull; }

#pragma unroll 4
    for (int k4 = 0; k4 < K; k4 += 4) {
        ulonglong2 wv[4];
#pragma unroll
        for (int t = 0; t < 4; t++)
            wv[t] = __ldg(reinterpret_cast<const ulonglong2*>(&W[(k4 + t) * N + j0]));
#pragma unroll
        for (int i = 0; i < RT; i++) {
            const int row = rg + i * RG;
            if (row < nrows) {        // warp-uniform
                float4 av = __ldg(reinterpret_cast<const float4*>(
                    &gbase[(size_t)rows[row] * K + k4]));
                unsigned long long pa0 = pack2(av.x), pa1 = pack2(av.y);
                unsigned long long pa2 = pack2(av.z), pa3 = pack2(av.w);
                ffma2(acc2[i][0], pa0, wv[0].x); ffma2(acc2[i][1], pa0, wv[0].y);
                ffma2(acc2[i][0], pa1, wv[1].x); ffma2(acc2[i][1], pa1, wv[1].y);
                ffma2(acc2[i][0], pa2, wv[2].x); ffma2(acc2[i][1], pa2, wv[2].y);
                ffma2(acc2[i][0], pa3, wv[3].x); ffma2(acc2[i][1], pa3, wv[3].y);
            }
        }
    }

    const float4 bv = __ldg(reinterpret_cast<const float4*>(&bias[j0]));
#pragma unroll
    for (int i = 0; i < RT; i++) {
        const int row = rg + i * RG;
        if (row < nrows) {
            float a0, a1v, a2v, a3;
            unpack2(acc2[i][0], a0, a1v);
            unpack2(acc2[i][1], a2v, a3);
            out[(size_t)row * N + j0 + 0] = a0  + bv.x;
            out[(size_t)row * N + j0 + 1] = a1v + bv.y;
            out[(size_t)row * N + j0 + 2] = a2v + bv.z;
            out[(size_t)row * N + j0 + 3] = a3  + bv.w;
        }
    }
}

// In-place LayerNorm + ReLU; one warp per row; works on smem OR gmem.
template<int N>
__device__ __forceinline__ void ln_relu(float* buf, const float* __restrict__ g,
                                        const float* __restrict__ bt, int rows) {
    const int warp = threadIdx.x >> 5;
    const int lane = threadIdx.x & 31;
    for (int r = warp; r < rows; r += NT / 32) {
        float* row = buf + (size_t)r * N;
        float s = 0.f;
#pragma unroll
        for (int j = lane; j < N; j += 32) s += row[j];
#pragma unroll
        for (int o = 16; o > 0; o >>= 1) s += __shfl_xor_sync(0xffffffffu, s, o);
        const float m = s * (1.0f / N);
        float v = 0.f;
#pragma unroll
        for (int j = lane; j < N; j += 32) { float d = row[j] - m; v = fmaf(d, d, v); }
#pragma unroll
        for (int o = 16; o > 0; o >>= 1) v += __shfl_xor_sync(0xffffffffu, v, o);
        const float rs = rsqrtf(v * (1.0f / N) + 1e-5f);
#pragma unroll
        for (int j = lane; j < N; j += 32) {
            float val = (row[j] - m) * rs * g[j] + bt[j];
            row[j] = val > 0.f ? val : 0.f;
        }
    }
}

// ---------------- K1: backbone (32 rows/CTA, 3 CTAs/SM) ----------------
struct K1S {
    float xs[32][8];
    float w1s[5 * 512];
    float a1[32 * 512];
};  // 75KB

__global__ void __launch_bounds__(NT, 3) k1_backbone(Params p) {
    extern __shared__ char sm[];
    K1S& s = *reinterpret_cast<K1S*>(sm);
    const int tid = threadIdx.x;
    const int row0 = blockIdx.x * 32;

    if (blockIdx.x == 0 && tid < NE) g_cnt[tid] = 0;  // routing counters

    for (int i = tid; i < 32 * 5; i += NT) s.xs[i / 5][i % 5] = p.x[(size_t)row0 * 5 + i];
    for (int i = tid; i < 5 * 512; i += NT) s.w1s[i] = p.bW1[i];
    __syncthreads();

    for (int i = tid; i < 32 * 512; i += NT) {
        const int r = i >> 9, j = i & 511;
        float acc = __ldg(&p.bb1[j]);
#pragma unroll
        for (int k = 0; k < 5; k++) acc = fmaf(s.xs[r][k], s.w1s[k * 512 + j], acc);
        s.a1[i] = acc;
    }
    __syncthreads();
    ln_relu<512>(s.a1, p.bg1, p.bbt1, 32);
    __syncthreads();

    float* a2blk = g_a2 + (size_t)row0 * 256;
    gemm_g<512, 256, 8, 32>(p.bW2, p.bb2, s.a1, a2blk, 32);
    __syncthreads();
    ln_relu<256>(a2blk, p.bg2, p.bbt2, 32);
}

// ---------------- K2: class chain + routing (64 rows/CTA) ----------------
struct K2S {
    float c1[64 * 128];
    float c2[64 * 128];
    float cls[64][4];
    int lcnt[NE];
    int lbi[64];
    int lslot[64];
    int base[NE];
};  // ~66KB

__global__ void __launch_bounds__(NT, 3) k2_class(Params p) {
    extern __shared__ char sm[];
    K2S& s = *reinterpret_cast<K2S*>(sm);
    const int tid = threadIdx.x;
    const int row0 = blockIdx.x * 64;
    const float* a2blk = g_a2 + (size_t)row0 * 256;

    gemm_g<256, 128, 8, 64>(p.cW1, p.cb1, a2blk, s.c1, 64);
    __syncthreads();
    ln_relu<128>(s.c1, p.cg1, p.cbt1, 64);
    __syncthreads();
    gemm_g<128, 128, 8, 64>(p.cW2, p.cb2, s.c1, s.c2, 64);
    __syncthreads();
    ln_relu<128>(s.c2, p.cg2, p.cbt2, 64);
    // c1 free (consumed before bar above): stage chW
    for (int i = tid; i < 512; i += NT) s.c1[i] = p.chW[i];
    if (tid < NE) s.lcnt[tid] = 0;
    __syncthreads();

    // head: 64 rows x 4 cols = 256 threads
    {
        const int r = tid >> 2, j = tid & 3;
        float acc = __ldg(&p.chb[j]);
        const float* c2r = s.c2 + r * 128;
#pragma unroll 8
        for (int k = 0; k < 128; k++) acc = fmaf(c2r[k], s.c1[k * 4 + j], acc);
        s.cls[r][j] = acc;
        p.out[(size_t)(row0 + r) * 4 + j] = acc;
    }
    __syncthreads();

    if (tid < 64) {
        float best = s.cls[tid][0]; int bi = 0;
#pragma unroll
        for (int j = 1; j < 4; j++)
            if (s.cls[tid][j] > best) { best = s.cls[tid][j]; bi = j; }
        s.lbi[tid] = bi;
        s.lslot[tid] = atomicAdd(&s.lcnt[bi], 1);
    }
    __syncthreads();
    if (tid < NE) s.base[tid] = atomicAdd(&g_cnt[tid], s.lcnt[tid]);
    __syncthreads();
    if (tid < 64) {
        const int bi = s.lbi[tid];
        g_elist[bi][s.base[bi] + s.lslot[tid]] = row0 + tid;
    }
}

// ---------------- K3: routed reg experts (64 rows/CTA segment) ----------------
struct K3S {
    float c1[64 * 128];
    float c2[64 * 128];
    float cls[64][4];
    int rows[64];
};  // ~66KB

__global__ void __launch_bounds__(NT, 3) k3_expert(Params p) {
    const int e = blockIdx.y;
    const int cnt = g_cnt[e];
    const int r0 = blockIdx.x * 64;
    if (r0 >= cnt) return;                   // uniform early exit (no syncs yet)
    const int ne = min(64, cnt - r0);

    extern __shared__ char sm[];
    K3S& s = *reinterpret_cast<K3S*>(sm);
    const int tid = threadIdx.x;

    if (tid < ne) s.rows[tid] = g_elist[e][r0 + tid];
    __syncthreads();

    gemm_idx<256, 128, 8, 64>(p.rW1 + e * 256 * 128, p.rb1 + e * 128,
                              g_a2, s.rows, s.c1, ne);
    __syncthreads();
    ln_relu<128>(s.c1, p.rg1 + e * 128, p.rbt1 + e * 128, ne);
    __syncthreads();
    gemm_g<128, 128, 8, 64>(p.rW2 + e * 128 * 128, p.rb2 + e * 128, s.c1, s.c2, ne);
    __syncthreads();
    ln_relu<128>(s.c2, p.rg2 + e * 128, p.rbt2 + e * 128, ne);
    for (int i = tid; i < 384; i += NT) s.c1[i] = p.rhW[e * 384 + i];
    __syncthreads();

    if (tid < ne * 3) {
        const int i = tid / 3, j = tid - i * 3;
        float acc = __ldg(&p.rhb[e * 3 + j]);
        const float* c2r = s.c2 + i * 128;
#pragma unroll 8
        for (int k = 0; k < 128; k++) acc = fmaf(c2r[k], s.c1[k * 3 + j], acc);
        s.cls[i][j] = acc;
    }
    __syncthreads();
    if (tid < ne) {
        const float v0 = s.cls[tid][0], v1 = s.cls[tid][1], v2 = s.cls[tid][2];
        const float m = fmaxf(v0, fmaxf(v1, v2));
        const float e0 = expf(v0 - m), e1 = expf(v1 - m), e2 = expf(v2 - m);
        const float inv = 1.f / (e0 + e1 + e2);
        float* o = p.out + (size_t)Bn * 4 + (size_t)s.rows[tid] * 3;
        o[0] = e0 * inv; o[1] = e1 * inv; o[2] = e2 * inv;
    }
}

// ---------------- input-order guard (insertion order matched) ----------------
static const int SZ_A[29] = {655360,2560,512,512,512,131072,256,256,256,32768,
                             128,128,128,16384,128,128,128,512,4,131072,
                             512,512,512,65536,512,512,512,1536,12};
static const int PERM_A[29] = {0,1,2,3,4,5,6,7,8,9,10,11,12,13,14,15,16,17,18,
                               19,20,21,22,23,24,25,26,27,28};
static const int SZ_B[29] = {2560,131072,512,256,512,256,512,256,32768,16384,
                             128,128,128,128,128,128,512,4,131072,65536,
                             512,512,512,512,512,512,1536,12,655360};
static const int PERM_B[29] = {28,0,2,6,4,1,3,7,5,8,10,14,12,9,11,15,13,16,17,
                               18,20,24,22,19,21,25,23,26,27};
static const int SZ_C[29] = {512,256,512,256,512,256,2560,131072,128,128,128,
                             128,128,128,4,512,32768,16384,512,512,512,512,
                             512,512,12,1536,131072,65536,655360};
static const int PERM_C[29] = {28,6,0,4,2,7,1,5,3,16,8,12,10,17,9,13,11,15,14,
                               26,18,22,20,27,19,23,21,25,24};

}  // namespace

extern "C" void kernel_launch(void* const* d_in, const int* in_sizes, int n_in,
                              void* d_out, int out_size) {
    const int* perm = PERM_A;
    bool mA = true, mB = true, mC = true;
    for (int i = 0; i < 29 && i < n_in; i++) {
        if (in_sizes[i] != SZ_A[i]) mA = false;
        if (in_sizes[i] != SZ_B[i]) mB = false;
        if (in_sizes[i] != SZ_C[i]) mC = false;
    }
    if (mA) perm = PERM_A;
    else if (mB) perm = PERM_B;
    else if (mC) perm = PERM_C;

    const float* q[29];
    for (int i = 0; i < 29; i++) q[i] = (const float*)d_in[perm[i]];

    Params p;
    p.x    = q[0];  p.bW1  = q[1];  p.bb1  = q[2];  p.bg1  = q[3];  p.bbt1 = q[4];
    p.bW2  = q[5];  p.bb2  = q[6];  p.bg2  = q[7];  p.bbt2 = q[8];
    p.cW1  = q[9];  p.cb1  = q[10]; p.cg1  = q[11]; p.cbt1 = q[12];
    p.cW2  = q[13]; p.cb2  = q[14]; p.cg2  = q[15]; p.cbt2 = q[16];
    p.chW  = q[17]; p.chb  = q[18];
    p.rW1  = q[19]; p.rb1  = q[20]; p.rg1  = q[21]; p.rbt1 = q[22];
    p.rW2  = q[23]; p.rb2  = q[24]; p.rg2  = q[25]; p.rbt2 = q[26];
    p.rhW  = q[27]; p.rhb  = q[28];
    p.out  = (float*)d_out;

    static bool attr_done = false;
    if (!attr_done) {
        cudaFuncSetAttribute(k1_backbone, cudaFuncAttributeMaxDynamicSharedMemorySize,
                             (int)sizeof(K1S));
        cudaFuncSetAttribute(k2_class, cudaFuncAttributeMaxDynamicSharedMemorySize,
                             (int)sizeof(K2S));
        cudaFuncSetAttribute(k3_expert, cudaFuncAttributeMaxDynamicSharedMemorySize,
                             (int)sizeof(K3S));
        attr_done = true;
    }

    k1_backbone<<<Bn / 32, NT, sizeof(K1S)>>>(p);
    k2_class<<<Bn / 64, NT, sizeof(K2S)>>>(p);
    dim3 g3(Bn / 64, NE);
    k3_expert<<<g3, NT, sizeof(K3S)>>>(p);
}

// round 17
// speedup vs baseline: 1.1717x; 1.1717x over previous
#include <cuda_runtime.h>
#include <cstdint>

namespace {

constexpr int Bn = 131072;
constexpr int NE = 4;

// global scratch (static __device__ allowed; no runtime alloc)
__device__ float g_a2[(size_t)Bn * 256];   // shared features, 134MB
__device__ int   g_elist[NE][Bn];          // per-expert compact row lists
__device__ int   g_cnt[NE];                // per-expert counts

struct Params {
    const float *x, *bW1, *bb1, *bg1, *bbt1, *bW2, *bb2, *bg2, *bbt2;
    const float *cW1, *cb1, *cg1, *cbt1, *cW2, *cb2, *cg2, *cbt2, *chW, *chb;
    const float *rW1, *rb1, *rg1, *rbt1, *rW2, *rb2, *rg2, *rbt2, *rhW, *rhb;
    float* out;
};

// ---- packed f32x2 helpers (bit-exact per-lane fp32 FMA) ----
__device__ __forceinline__ void ffma2(unsigned long long& d,
                                      unsigned long long a,
                                      unsigned long long b) {
    asm("fma.rn.f32x2 %0, %1, %2, %0;" : "+l"(d) : "l"(a), "l"(b));
}
__device__ __forceinline__ unsigned long long pack2(float v) {
    unsigned long long r;
    asm("mov.b64 %0, {%1, %1};" : "=l"(r) : "f"(v));
    return r;
}
__device__ __forceinline__ void unpack2(unsigned long long v, float& lo, float& hi) {
    asm("mov.b64 {%0, %1}, %2;" : "=f"(lo), "=f"(hi) : "l"(v));
}

// out[row][N] = act[row][K] @ W[K][N] + bias for row < nrows.
// act: smem or gmem (warp-broadcast reads), compact stride K.
// W,bias gmem via __ldg. Row map row = rg + i*RG (rg warp-uniform guards).
template<int K, int N, int RT, int TMv, int NTv>
__device__ __forceinline__ void gemm_g(const float* __restrict__ W,
                                       const float* __restrict__ bias,
                                       const float* act, float* out, int nrows) {
    constexpr int CG = N / 4;
    constexpr int RG = NTv / CG;
    static_assert(RG * RT == TMv, "row coverage");

    const int tid = threadIdx.x;
    const int cg = tid % CG;
    const int rg = tid / CG;          // warp-uniform
    const int j0 = cg * 4;

    unsigned long long acc2[RT][2];
#pragma unroll
    for (int i = 0; i < RT; i++) { acc2[i][0] = 0ull; acc2[i][1] = 0ull; }

#pragma unroll 4
    for (int k4 = 0; k4 < K; k4 += 4) {
        ulonglong2 wv[4];
#pragma unroll
        for (int t = 0; t < 4; t++)
            wv[t] = __ldg(reinterpret_cast<const ulonglong2*>(&W[(k4 + t) * N + j0]));
#pragma unroll
        for (int i = 0; i < RT; i++) {
            const int row = rg + i * RG;
            if (row < nrows) {        // warp-uniform
                float4 av = *reinterpret_cast<const float4*>(&act[(size_t)row * K + k4]);
                unsigned long long pa0 = pack2(av.x), pa1 = pack2(av.y);
                unsigned long long pa2 = pack2(av.z), pa3 = pack2(av.w);
                ffma2(acc2[i][0], pa0, wv[0].x); ffma2(acc2[i][1], pa0, wv[0].y);
                ffma2(acc2[i][0], pa1, wv[1].x); ffma2(acc2[i][1], pa1, wv[1].y);
                ffma2(acc2[i][0], pa2, wv[2].x); ffma2(acc2[i][1], pa2, wv[2].y);
                ffma2(acc2[i][0], pa3, wv[3].x); ffma2(acc2[i][1], pa3, wv[3].y);
            }
        }
    }

    const float4 bv = __ldg(reinterpret_cast<const float4*>(&bias[j0]));
#pragma unroll
    for (int i = 0; i < RT; i++) {
        const int row = rg + i * RG;
        if (row < nrows) {
            float a0, a1v, a2v, a3;
            unpack2(acc2[i][0], a0, a1v);
            unpack2(acc2[i][1], a2v, a3);
            out[(size_t)row * N + j0 + 0] = a0  + bv.x;
            out[(size_t)row * N + j0 + 1] = a1v + bv.y;
            out[(size_t)row * N + j0 + 2] = a2v + bv.z;
            out[(size_t)row * N + j0 + 3] = a3  + bv.w;
        }
    }
}

// Same as gemm_g but rows gathered from gbase via index list (smem).
template<int K, int N, int RT, int TMv, int NTv>
__device__ __forceinline__ void gemm_idx(const float* __restrict__ W,
                                         const float* __restrict__ bias,
                                         const float* __restrict__ gbase,
                                         const int* rows,
                                         float* out, int nrows) {
    constexpr int CG = N / 4;
    constexpr int RG = NTv / CG;
    static_assert(RG * RT == TMv, "row coverage");

    const int tid = threadIdx.x;
    const int cg = tid % CG;
    const int rg = tid / CG;          // warp-uniform
    const int j0 = cg * 4;

    unsigned long long acc2[RT][2];
#pragma unroll
    for (int i = 0; i < RT; i++) { acc2[i][0] = 0ull; acc2[i][1] = 0ull; }

#pragma unroll 4
    for (int k4 = 0; k4 < K; k4 += 4) {
        ulonglong2 wv[4];
#pragma unroll
        for (int t = 0; t < 4; t++)
            wv[t] = __ldg(reinterpret_cast<const ulonglong2*>(&W[(k4 + t) * N + j0]));
#pragma unroll
        for (int i = 0; i < RT; i++) {
            const int row = rg + i * RG;
            if (row < nrows) {        // warp-uniform
                float4 av = __ldg(reinterpret_cast<const float4*>(
                    &gbase[(size_t)rows[row] * K + k4]));
                unsigned long long pa0 = pack2(av.x), pa1 = pack2(av.y);
                unsigned long long pa2 = pack2(av.z), pa3 = pack2(av.w);
                ffma2(acc2[i][0], pa0, wv[0].x); ffma2(acc2[i][1], pa0, wv[0].y);
                ffma2(acc2[i][0], pa1, wv[1].x); ffma2(acc2[i][1], pa1, wv[1].y);
                ffma2(acc2[i][0], pa2, wv[2].x); ffma2(acc2[i][1], pa2, wv[2].y);
                ffma2(acc2[i][0], pa3, wv[3].x); ffma2(acc2[i][1], pa3, wv[3].y);
            }
        }
    }

    const float4 bv = __ldg(reinterpret_cast<const float4*>(&bias[j0]));
#pragma unroll
    for (int i = 0; i < RT; i++) {
        const int row = rg + i * RG;
        if (row < nrows) {
            float a0, a1v, a2v, a3;
            unpack2(acc2[i][0], a0, a1v);
            unpack2(acc2[i][1], a2v, a3);
            out[(size_t)row * N + j0 + 0] = a0  + bv.x;
            out[(size_t)row * N + j0 + 1] = a1v + bv.y;
            out[(size_t)row * N + j0 + 2] = a2v + bv.z;
            out[(size_t)row * N + j0 + 3] = a3  + bv.w;
        }
    }
}

// In-place LayerNorm + ReLU; one warp per row; smem OR gmem pointer.
template<int N, int NTv>
__device__ __forceinline__ void ln_relu(float* buf, const float* __restrict__ g,
                                        const float* __restrict__ bt, int rows) {
    const int warp = threadIdx.x >> 5;
    const int lane = threadIdx.x & 31;
    for (int r = warp; r < rows; r += NTv / 32) {
        float* row = buf + (size_t)r * N;
        float s = 0.f;
#pragma unroll
        for (int j = lane; j < N; j += 32) s += row[j];
#pragma unroll
        for (int o = 16; o > 0; o >>= 1) s += __shfl_xor_sync(0xffffffffu, s, o);
        const float m = s * (1.0f / N);
        float v = 0.f;
#pragma unroll
        for (int j = lane; j < N; j += 32) { float d = row[j] - m; v = fmaf(d, d, v); }
#pragma unroll
        for (int o = 16; o > 0; o >>= 1) v += __shfl_xor_sync(0xffffffffu, v, o);
        const float rs = rsqrtf(v * (1.0f / N) + 1e-5f);
#pragma unroll
        for (int j = lane; j < N; j += 32) {
            float val = (row[j] - m) * rs * g[j] + bt[j];
            row[j] = val > 0.f ? val : 0.f;
        }
    }
}

// ---------------- K1: backbone (32 rows/CTA, NT=256, 3 CTAs/SM) ----------------
struct K1S {
    float xs[32][8];
    float w1s[5 * 512];
    float a1[32 * 512];
};  // 75KB

__global__ void __launch_bounds__(256, 3) k1_backbone(Params p) {
    extern __shared__ char sm[];
    K1S& s = *reinterpret_cast<K1S*>(sm);
    const int tid = threadIdx.x;
    const int row0 = blockIdx.x * 32;

    if (blockIdx.x == 0 && tid < NE) g_cnt[tid] = 0;  // routing counters

    for (int i = tid; i < 32 * 5; i += 256) s.xs[i / 5][i % 5] = p.x[(size_t)row0 * 5 + i];
    for (int i = tid; i < 5 * 512; i += 256) s.w1s[i] = p.bW1[i];
    __syncthreads();

    for (int i = tid; i < 32 * 512; i += 256) {
        const int r = i >> 9, j = i & 511;
        float acc = __ldg(&p.bb1[j]);
#pragma unroll
        for (int k = 0; k < 5; k++) acc = fmaf(s.xs[r][k], s.w1s[k * 512 + j], acc);
        s.a1[i] = acc;
    }
    __syncthreads();
    ln_relu<512, 256>(s.a1, p.bg1, p.bbt1, 32);
    __syncthreads();

    float* a2blk = g_a2 + (size_t)row0 * 256;
    gemm_g<512, 256, 8, 32, 256>(p.bW2, p.bb2, s.a1, a2blk, 32);
    __syncthreads();
    ln_relu<256, 256>(a2blk, p.bg2, p.bbt2, 32);
}

// ---------------- K2: class chain + routing (32 rows/CTA, NT=128) ----------------
struct K2S {
    float c1[32 * 128];
    float c2[32 * 128];
    float cls[32][4];
    int lcnt[NE];
    int lbi[32];
    int lslot[32];
    int base[NE];
};  // ~33.5KB

__global__ void __launch_bounds__(128, 5) k2_class(Params p) {
    extern __shared__ char sm[];
    K2S& s = *reinterpret_cast<K2S*>(sm);
    const int tid = threadIdx.x;
    const int row0 = blockIdx.x * 32;
    const float* a2blk = g_a2 + (size_t)row0 * 256;

    gemm_g<256, 128, 8, 32, 128>(p.cW1, p.cb1, a2blk, s.c1, 32);
    __syncthreads();
    ln_relu<128, 128>(s.c1, p.cg1, p.cbt1, 32);
    __syncthreads();
    gemm_g<128, 128, 8, 32, 128>(p.cW2, p.cb2, s.c1, s.c2, 32);
    __syncthreads();
    ln_relu<128, 128>(s.c2, p.cg2, p.cbt2, 32);
    // c1 free (consumed before bar above): stage chW
    for (int i = tid; i < 512; i += 128) s.c1[i] = p.chW[i];
    if (tid < NE) s.lcnt[tid] = 0;
    __syncthreads();

    // head: 32 rows x 4 cols = 128 threads exactly
    {
        const int r = tid >> 2, j = tid & 3;
        float acc = __ldg(&p.chb[j]);
        const float* c2r = s.c2 + r * 128;
#pragma unroll 8
        for (int k = 0; k < 128; k++) acc = fmaf(c2r[k], s.c1[k * 4 + j], acc);
        s.cls[r][j] = acc;
        p.out[(size_t)(row0 + r) * 4 + j] = acc;
    }
    __syncthreads();

    if (tid < 32) {
        float best = s.cls[tid][0]; int bi = 0;
#pragma unroll
        for (int j = 1; j < 4; j++)
            if (s.cls[tid][j] > best) { best = s.cls[tid][j]; bi = j; }
        s.lbi[tid] = bi;
        s.lslot[tid] = atomicAdd(&s.lcnt[bi], 1);
    }
    __syncthreads();
    if (tid < NE) s.base[tid] = atomicAdd(&g_cnt[tid], s.lcnt[tid]);
    __syncthreads();
    if (tid < 32) {
        const int bi = s.lbi[tid];
        g_elist[bi][s.base[bi] + s.lslot[tid]] = row0 + tid;
    }
}

// ---------------- K3: routed reg experts (32 rows/segment, NT=128) ----------------
struct K3S {
    float c1[32 * 128];
    float c2[32 * 128];
    float cls[32][4];
    int rows[32];
};  // ~33KB

__global__ void __launch_bounds__(128, 5) k3_expert(Params p) {
    const int e = blockIdx.y;
    const int cnt = g_cnt[e];
    const int r0 = blockIdx.x * 32;
    if (r0 >= cnt) return;                   // uniform early exit (no syncs yet)
    const int ne = min(32, cnt - r0);

    extern __shared__ char sm[];
    K3S& s = *reinterpret_cast<K3S*>(sm);
    const int tid = threadIdx.x;

    if (tid < ne) s.rows[tid] = g_elist[e][r0 + tid];
    __syncthreads();

    gemm_idx<256, 128, 8, 32, 128>(p.rW1 + e * 256 * 128, p.rb1 + e * 128,
                                   g_a2, s.rows, s.c1, ne);
    __syncthreads();
    ln_relu<128, 128>(s.c1, p.rg1 + e * 128, p.rbt1 + e * 128, ne);
    __syncthreads();
    gemm_g<128, 128, 8, 32, 128>(p.rW2 + e * 128 * 128, p.rb2 + e * 128,
                                 s.c1, s.c2, ne);
    __syncthreads();
    ln_relu<128, 128>(s.c2, p.rg2 + e * 128, p.rbt2 + e * 128, ne);
    for (int i = tid; i < 384; i += 128) s.c1[i] = p.rhW[e * 384 + i];
    __syncthreads();

    if (tid < ne * 3) {
        const int i = tid / 3, j = tid - i * 3;
        float acc = __ldg(&p.rhb[e * 3 + j]);
        const float* c2r = s.c2 + i * 128;
#pragma unroll 8
        for (int k = 0; k < 128; k++) acc = fmaf(c2r[k], s.c1[k * 3 + j], acc);
        s.cls[i][j] = acc;
    }
    __syncthreads();
    if (tid < ne) {
        const float v0 = s.cls[tid][0], v1 = s.cls[tid][1], v2 = s.cls[tid][2];
        const float m = fmaxf(v0, fmaxf(v1, v2));
        const float e0 = expf(v0 - m), e1 = expf(v1 - m), e2 = expf(v2 - m);
        const float inv = 1.f / (e0 + e1 + e2);
        float* o = p.out + (size_t)Bn * 4 + (size_t)s.rows[tid] * 3;
        o[0] = e0 * inv; o[1] = e1 * inv; o[2] = e2 * inv;
    }
}

// ---------------- input-order guard (insertion order matched) ----------------
static const int SZ_A[29] = {655360,2560,512,512,512,131072,256,256,256,32768,
                             128,128,128,16384,128,128,128,512,4,131072,
                             512,512,512,65536,512,512,512,1536,12};
static const int PERM_A[29] = {0,1,2,3,4,5,6,7,8,9,10,11,12,13,14,15,16,17,18,
                               19,20,21,22,23,24,25,26,27,28};
static const int SZ_B[29] = {2560,131072,512,256,512,256,512,256,32768,16384,
                             128,128,128,128,128,128,512,4,131072,65536,
                             512,512,512,512,512,512,1536,12,655360};
static const int PERM_B[29] = {28,0,2,6,4,1,3,7,5,8,10,14,12,9,11,15,13,16,17,
                               18,20,24,22,19,21,25,23,26,27};
static const int SZ_C[29] = {512,256,512,256,512,256,2560,131072,128,128,128,
                             128,128,128,4,512,32768,16384,512,512,512,512,
                             512,512,12,1536,131072,65536,655360};
static const int PERM_C[29] = {28,6,0,4,2,7,1,5,3,16,8,12,10,17,9,13,11,15,14,
                               26,18,22,20,27,19,23,21,25,24};

}  // namespace

extern "C" void kernel_launch(void* const* d_in, const int* in_sizes, int n_in,
                              void* d_out, int out_size) {
    const int* perm = PERM_A;
    bool mA = true, mB = true, mC = true;
    for (int i = 0; i < 29 && i < n_in; i++) {
        if (in_sizes[i] != SZ_A[i]) mA = false;
        if (in_sizes[i] != SZ_B[i]) mB = false;
        if (in_sizes[i] != SZ_C[i]) mC = false;
    }
    if (mA) perm = PERM_A;
    else if (mB) perm = PERM_B;
    else if (mC) perm = PERM_C;

    const float* q[29];
    for (int i = 0; i < 29; i++) q[i] = (const float*)d_in[perm[i]];

    Params p;
    p.x    = q[0];  p.bW1  = q[1];  p.bb1  = q[2];  p.bg1  = q[3];  p.bbt1 = q[4];
    p.bW2  = q[5];  p.bb2  = q[6];  p.bg2  = q[7];  p.bbt2 = q[8];
    p.cW1  = q[9];  p.cb1  = q[10]; p.cg1  = q[11]; p.cbt1 = q[12];
    p.cW2  = q[13]; p.cb2  = q[14]; p.cg2  = q[15]; p.cbt2 = q[16];
    p.chW  = q[17]; p.chb  = q[18];
    p.rW1  = q[19]; p.rb1  = q[20]; p.rg1  = q[21]; p.rbt1 = q[22];
    p.rW2  = q[23]; p.rb2  = q[24]; p.rg2  = q[25]; p.rbt2 = q[26];
    p.rhW  = q[27]; p.rhb  = q[28];
    p.out  = (float*)d_out;

    static bool attr_done = false;
    if (!attr_done) {
        cudaFuncSetAttribute(k1_backbone, cudaFuncAttributeMaxDynamicSharedMemorySize,
                             (int)sizeof(K1S));
        cudaFuncSetAttribute(k2_class, cudaFuncAttributeMaxDynamicSharedMemorySize,
                             (int)sizeof(K2S));
        cudaFuncSetAttribute(k3_expert, cudaFuncAttributeMaxDynamicSharedMemorySize,
                             (int)sizeof(K3S));
        attr_done = true;
    }

    k1_backbone<<<Bn / 32, 256, sizeof(K1S)>>>(p);
    k2_class<<<Bn / 32, 128, sizeof(K2S)>>>(p);
    dim3 g3(Bn / 32, NE);
    k3_expert<<<g3, 128, sizeof(K3S)>>>(p);
}